// round 1
// baseline (speedup 1.0000x reference)
#include <cuda_runtime.h>
#include <cuda_bf16.h>
#include <math.h>

// Problem dims
#define Bz   2
#define Sq   2048
#define Dm   1024
#define Hn   16
#define DH   64
#define DFF  4096
#define Mrows (Bz * Sq)      // 4096
#define BH   (Bz * Hn)       // 32

// ---------------- scratch (static device globals: allocation-free rule) ------
__device__ float g_xn[(size_t)Mrows * Dm];          // 16 MB (rmsnorm out, reused)
__device__ float g_qkv[(size_t)Mrows * 3 * Dm];     // 48 MB
__device__ float g_scores[(size_t)BH * Sq * Sq];    // 512 MB
__device__ float g_attnout[(size_t)Mrows * Dm];     // 16 MB
__device__ float g_x2[(size_t)Mrows * Dm];          // 16 MB
__device__ float g_h[(size_t)Mrows * DFF];          // 64 MB

// ---------------- RMSNorm ----------------------------------------------------
__global__ __launch_bounds__(256)
void rmsnorm_kernel(const float* __restrict__ x, const float* __restrict__ scale,
                    float* __restrict__ out)
{
    int row = blockIdx.x;
    const float* xr = x + (size_t)row * Dm;
    float ss = 0.f;
    #pragma unroll
    for (int i = threadIdx.x; i < Dm; i += 256) { float v = xr[i]; ss += v * v; }
    __shared__ float red[256];
    red[threadIdx.x] = ss; __syncthreads();
    #pragma unroll
    for (int s = 128; s > 0; s >>= 1) {
        if (threadIdx.x < s) red[threadIdx.x] += red[threadIdx.x + s];
        __syncthreads();
    }
    float rms = rsqrtf(red[0] * (1.0f / Dm) + 1e-8f);
    float* orow = out + (size_t)row * Dm;
    #pragma unroll
    for (int i = threadIdx.x; i < Dm; i += 256)
        orow[i] = scale[i] * xr[i] * rms;
}

// ---------------- Generic tiled GEMM: C = A[M,K] @ B[K,N] (+bias)(+resid)(gelu)
// EPI: 0 = bias only, 1 = bias + residual, 2 = bias + exact gelu
template<int EPI>
__global__ __launch_bounds__(256)
void gemm_kernel(const float* __restrict__ A, const float* __restrict__ Bm,
                 const float* __restrict__ bias, const float* __restrict__ resid,
                 float* __restrict__ C, int M, int N, int K)
{
    __shared__ float As[16][65];   // As[k][m]
    __shared__ float Bs[16][65];   // Bs[k][n]
    const int bm = blockIdx.y * 64, bn = blockIdx.x * 64;
    const int tid = threadIdx.x;
    const int tx = tid & 15, ty = tid >> 4;
    float acc[4][4] = {};

    for (int k0 = 0; k0 < K; k0 += 16) {
        // A tile: 64 rows x 16 cols -> transposed into As[k][m]
        {
            int j = tid & 15, i0 = tid >> 4;
            #pragma unroll
            for (int p = 0; p < 4; p++) {
                int m = i0 + p * 16;
                As[j][m] = A[(size_t)(bm + m) * K + k0 + j];
            }
        }
        // B tile: 16 rows x 64 cols
        {
            int j = tid & 63, i0 = tid >> 6;
            #pragma unroll
            for (int p = 0; p < 4; p++) {
                int kk = i0 + p * 4;
                Bs[kk][j] = Bm[(size_t)(k0 + kk) * N + bn + j];
            }
        }
        __syncthreads();
        #pragma unroll
        for (int kk = 0; kk < 16; kk++) {
            float a[4], b[4];
            #pragma unroll
            for (int i = 0; i < 4; i++) a[i] = As[kk][ty * 4 + i];
            #pragma unroll
            for (int j = 0; j < 4; j++) b[j] = Bs[kk][tx * 4 + j];
            #pragma unroll
            for (int i = 0; i < 4; i++)
                #pragma unroll
                for (int j = 0; j < 4; j++) acc[i][j] += a[i] * b[j];
        }
        __syncthreads();
    }

    #pragma unroll
    for (int i = 0; i < 4; i++) {
        int m = bm + ty * 4 + i;
        #pragma unroll
        for (int j = 0; j < 4; j++) {
            int n = bn + tx * 4 + j;
            float v = acc[i][j] + bias[n];
            if (EPI == 1) v += resid[(size_t)m * N + n];
            if (EPI == 2) v = 0.5f * v * (1.0f + erff(v * 0.70710678118654752f));
            C[(size_t)m * N + n] = v;
        }
    }
}

// ---------------- QK^T + scale + ALiBi ---------------------------------------
// scores[bh, s, t] = (q . k) / 8 - slope(h) * |s - t|
__global__ __launch_bounds__(256)
void qk_kernel(const float* __restrict__ qkv, float* __restrict__ scores)
{
    const int bh = blockIdx.z;
    const int b = bh / Hn, h = bh % Hn;
    const int s0 = blockIdx.y * 64, t0 = blockIdx.x * 64;
    __shared__ float qs[64][65];   // [d][s]
    __shared__ float ks[64][65];   // [d][t]
    const int tid = threadIdx.x, tx = tid & 15, ty = tid >> 4;
    const size_t qbase = (size_t)b * Sq * (3 * Dm) + (size_t)h * DH;
    {
        int d = tid & 63, r0 = tid >> 6;
        #pragma unroll
        for (int p = 0; p < 16; p++) {
            int r = r0 + p * 4;
            qs[d][r] = qkv[qbase + (size_t)(s0 + r) * (3 * Dm) + d];
            ks[d][r] = qkv[qbase + (size_t)(t0 + r) * (3 * Dm) + Dm + d];
        }
    }
    __syncthreads();
    float acc[4][4] = {};
    #pragma unroll 8
    for (int d = 0; d < 64; d++) {
        float a[4], bb[4];
        #pragma unroll
        for (int i = 0; i < 4; i++) a[i] = qs[d][ty * 4 + i];
        #pragma unroll
        for (int j = 0; j < 4; j++) bb[j] = ks[d][tx * 4 + j];
        #pragma unroll
        for (int i = 0; i < 4; i++)
            #pragma unroll
            for (int j = 0; j < 4; j++) acc[i][j] += a[i] * bb[j];
    }
    const float slope = exp2f(-0.5f * (float)(h + 1));
    const size_t obase = ((size_t)bh * Sq + s0) * Sq + t0;
    #pragma unroll
    for (int i = 0; i < 4; i++) {
        int si = s0 + ty * 4 + i;
        #pragma unroll
        for (int j = 0; j < 4; j++) {
            int tj = t0 + tx * 4 + j;
            scores[obase + (size_t)(ty * 4 + i) * Sq + tx * 4 + j] =
                acc[i][j] * 0.125f - slope * fabsf((float)(si - tj));
        }
    }
}

// ---------------- softmax over last dim (row length 2048) --------------------
__global__ __launch_bounds__(256)
void softmax_kernel(float* __restrict__ scores)
{
    float* p = scores + (size_t)blockIdx.x * Sq;
    float v[8];
    float mx = -1e30f;
    #pragma unroll
    for (int i = 0; i < 8; i++) { v[i] = p[threadIdx.x + i * 256]; mx = fmaxf(mx, v[i]); }
    __shared__ float red[256];
    red[threadIdx.x] = mx; __syncthreads();
    #pragma unroll
    for (int s = 128; s > 0; s >>= 1) {
        if (threadIdx.x < s) red[threadIdx.x] = fmaxf(red[threadIdx.x], red[threadIdx.x + s]);
        __syncthreads();
    }
    mx = red[0]; __syncthreads();
    float sum = 0.f;
    #pragma unroll
    for (int i = 0; i < 8; i++) { v[i] = __expf(v[i] - mx); sum += v[i]; }
    red[threadIdx.x] = sum; __syncthreads();
    #pragma unroll
    for (int s = 128; s > 0; s >>= 1) {
        if (threadIdx.x < s) red[threadIdx.x] += red[threadIdx.x + s];
        __syncthreads();
    }
    float inv = 1.0f / red[0];
    #pragma unroll
    for (int i = 0; i < 8; i++) p[threadIdx.x + i * 256] = v[i] * inv;
}

// ---------------- attn @ V ---------------------------------------------------
// attnout[(b*S+s)*D + h*64 + d] = sum_t attn[bh,s,t] * v[bh,t,d]
__global__ __launch_bounds__(256)
void av_kernel(const float* __restrict__ scores, const float* __restrict__ qkv,
               float* __restrict__ attnout)
{
    const int bh = blockIdx.y;
    const int b = bh / Hn, h = bh % Hn;
    const int s0 = blockIdx.x * 64;
    __shared__ float at[64][65];   // [t][s]
    __shared__ float vs[64][65];   // [t][d]
    const int tid = threadIdx.x, tx = tid & 15, ty = tid >> 4;
    float acc[4][4] = {};
    const size_t srow = ((size_t)bh * Sq + s0) * Sq;
    const size_t vbase = (size_t)b * Sq * (3 * Dm) + 2 * Dm + (size_t)h * DH;

    for (int t0 = 0; t0 < Sq; t0 += 64) {
        {
            int c = tid & 63, r0 = tid >> 6;
            #pragma unroll
            for (int p = 0; p < 16; p++) {
                int r = r0 + p * 4;
                at[c][r] = scores[srow + (size_t)r * Sq + t0 + c];          // t=c, s=r
                vs[r][c] = qkv[vbase + (size_t)(t0 + r) * (3 * Dm) + c];    // t=r, d=c
            }
        }
        __syncthreads();
        #pragma unroll 8
        for (int t = 0; t < 64; t++) {
            float a[4], bb[4];
            #pragma unroll
            for (int i = 0; i < 4; i++) a[i] = at[t][ty * 4 + i];
            #pragma unroll
            for (int j = 0; j < 4; j++) bb[j] = vs[t][tx * 4 + j];
            #pragma unroll
            for (int i = 0; i < 4; i++)
                #pragma unroll
                for (int j = 0; j < 4; j++) acc[i][j] += a[i] * bb[j];
        }
        __syncthreads();
    }
    const size_t obase = ((size_t)b * Sq + s0) * Dm + (size_t)h * DH;
    #pragma unroll
    for (int i = 0; i < 4; i++)
        #pragma unroll
        for (int j = 0; j < 4; j++)
            attnout[obase + (size_t)(ty * 4 + i) * Dm + tx * 4 + j] = acc[i][j];
}

// ---------------- host driver ------------------------------------------------
extern "C" void kernel_launch(void* const* d_in, const int* in_sizes, int n_in,
                              void* d_out, int out_size)
{
    const float* x      = (const float*)d_in[0];
    const float* scale1 = (const float*)d_in[1];
    const float* scale2 = (const float*)d_in[2];
    const float* w_qkv  = (const float*)d_in[3];
    const float* b_qkv  = (const float*)d_in[4];
    const float* w_out  = (const float*)d_in[5];
    const float* b_out  = (const float*)d_in[6];
    const float* w1     = (const float*)d_in[7];
    const float* b1     = (const float*)d_in[8];
    const float* w2     = (const float*)d_in[9];
    const float* b2     = (const float*)d_in[10];
    float* out = (float*)d_out;

    void *p_xn, *p_qkv, *p_scores, *p_attnout, *p_x2, *p_h;
    cudaGetSymbolAddress(&p_xn, g_xn);
    cudaGetSymbolAddress(&p_qkv, g_qkv);
    cudaGetSymbolAddress(&p_scores, g_scores);
    cudaGetSymbolAddress(&p_attnout, g_attnout);
    cudaGetSymbolAddress(&p_x2, g_x2);
    cudaGetSymbolAddress(&p_h, g_h);
    float* xn      = (float*)p_xn;
    float* qkv     = (float*)p_qkv;
    float* scores  = (float*)p_scores;
    float* attnout = (float*)p_attnout;
    float* x2      = (float*)p_x2;
    float* hbuf    = (float*)p_h;

    // 1) RMSNorm 1
    rmsnorm_kernel<<<Mrows, 256>>>(x, scale1, xn);

    // 2) QKV projection: [4096,1024] @ [1024,3072] + b
    gemm_kernel<0><<<dim3(3 * Dm / 64, Mrows / 64), 256>>>(
        xn, w_qkv, b_qkv, nullptr, qkv, Mrows, 3 * Dm, Dm);

    // 3) scores = QK^T/8 + alibi
    qk_kernel<<<dim3(Sq / 64, Sq / 64, BH), 256>>>(qkv, scores);

    // 4) softmax rows
    softmax_kernel<<<BH * Sq, 256>>>(scores);

    // 5) attn @ V -> [B,S,D] layout
    av_kernel<<<dim3(Sq / 64, BH), 256>>>(scores, qkv, attnout);

    // 6) out projection + residual(x): x2 = x + attnout @ w_out + b_out
    gemm_kernel<1><<<dim3(Dm / 64, Mrows / 64), 256>>>(
        attnout, w_out, b_out, x, x2, Mrows, Dm, Dm);

    // 7) RMSNorm 2
    rmsnorm_kernel<<<Mrows, 256>>>(x2, scale2, xn);

    // 8) FFN up + exact GELU: h = gelu(xn @ w1 + b1)
    gemm_kernel<2><<<dim3(DFF / 64, Mrows / 64), 256>>>(
        xn, w1, b1, nullptr, hbuf, Mrows, DFF, Dm);

    // 9) FFN down + residual(x2): out = x2 + h @ w2 + b2
    gemm_kernel<1><<<dim3(Dm / 64, Mrows / 64), 256>>>(
        hbuf, w2, b2, x2, out, Mrows, Dm, DFF);
}

// round 2
// speedup vs baseline: 3.2319x; 3.2319x over previous
#include <cuda_runtime.h>
#include <cuda_bf16.h>
#include <math.h>
#include <stdint.h>

// Problem dims
#define Bz   2
#define Sq   2048
#define Dm   1024
#define Hn   16
#define DH   64
#define DFF  4096
#define Mrows (Bz * Sq)      // 4096
#define BH   (Bz * Hn)       // 32

// ---------------- scratch ----------------------------------------------------
__device__ float g_xn[(size_t)Mrows * Dm];
__device__ float g_qkv[(size_t)Mrows * 3 * Dm];
__device__ float g_scores[(size_t)BH * Sq * Sq];
__device__ float g_attnout[(size_t)Mrows * Dm];
__device__ float g_x2[(size_t)Mrows * Dm];
__device__ float g_h[(size_t)Mrows * DFF];

// ---------------- helpers ----------------------------------------------------
__device__ __forceinline__ uint32_t f2tf32(float f) {
    uint32_t u;
    asm("cvt.rna.tf32.f32 %0, %1;" : "=r"(u) : "f"(f));
    return u;
}

__device__ __forceinline__ void mma_tf32(float c[4],
    uint32_t a0, uint32_t a1, uint32_t a2, uint32_t a3,
    uint32_t b0, uint32_t b1)
{
    asm volatile(
        "mma.sync.aligned.m16n8k8.row.col.f32.tf32.tf32.f32 "
        "{%0,%1,%2,%3}, {%4,%5,%6,%7}, {%8,%9}, {%0,%1,%2,%3};\n"
        : "+f"(c[0]), "+f"(c[1]), "+f"(c[2]), "+f"(c[3])
        : "r"(a0), "r"(a1), "r"(a2), "r"(a3), "r"(b0), "r"(b1));
}

// ---------------- RMSNorm ----------------------------------------------------
__global__ __launch_bounds__(256)
void rmsnorm_kernel(const float* __restrict__ x, const float* __restrict__ scale,
                    float* __restrict__ out)
{
    int row = blockIdx.x;
    const float* xr = x + (size_t)row * Dm;
    float ss = 0.f;
    #pragma unroll
    for (int i = threadIdx.x; i < Dm; i += 256) { float v = xr[i]; ss += v * v; }
    __shared__ float red[256];
    red[threadIdx.x] = ss; __syncthreads();
    #pragma unroll
    for (int s = 128; s > 0; s >>= 1) {
        if (threadIdx.x < s) red[threadIdx.x] += red[threadIdx.x + s];
        __syncthreads();
    }
    float rms = rsqrtf(red[0] * (1.0f / Dm) + 1e-8f);
    float* orow = out + (size_t)row * Dm;
    #pragma unroll
    for (int i = threadIdx.x; i < Dm; i += 256)
        orow[i] = scale[i] * xr[i] * rms;
}

// ---------------- TF32 tensor-core GEMM: C = A[M,K] @ B[K,N] -----------------
// EPI: 0 = +bias, 1 = +bias+residual, 2 = +bias then exact gelu
// Block tile 128x128, warp tile 64x32 (8 warps as 2m x 4n), K-chunk 32.
template<int EPI>
__global__ __launch_bounds__(256, 2)
void gemm_tc(const float* __restrict__ A, const float* __restrict__ Bm,
             const float* __restrict__ bias, const float* __restrict__ resid,
             float* __restrict__ C, int M, int N, int K)
{
    __shared__ uint32_t As[128][36];   // [m][k], pad 36 -> conflict-free frag loads
    __shared__ uint32_t Bs[32][136];   // [k][n], pad 136 -> conflict-free frag loads
    const int tid = threadIdx.x, warp = tid >> 5, lane = tid & 31;
    const int bm = blockIdx.y * 128, bn = blockIdx.x * 128;
    const int warpM = (warp & 1) * 64, warpN = (warp >> 1) * 32;
    const int r0 = lane >> 2, c0 = lane & 3;
    float c[4][4][4] = {};

    for (int k0 = 0; k0 < K; k0 += 32) {
        __syncthreads();
        // A chunk: 128 rows x 32 k (8 float4 per row) = 1024 float4 / 256 thr = 4 each
        #pragma unroll
        for (int p = 0; p < 4; p++) {
            int idx = tid + p * 256;
            int m = idx >> 3, k4 = idx & 7;
            float4 v = *(const float4*)&A[(size_t)(bm + m) * K + k0 + k4 * 4];
            As[m][k4 * 4 + 0] = f2tf32(v.x);
            As[m][k4 * 4 + 1] = f2tf32(v.y);
            As[m][k4 * 4 + 2] = f2tf32(v.z);
            As[m][k4 * 4 + 3] = f2tf32(v.w);
        }
        // B chunk: 32 k rows x 128 n (32 float4 per row)
        #pragma unroll
        for (int p = 0; p < 4; p++) {
            int idx = tid + p * 256;
            int k = idx >> 5, n4 = idx & 31;
            float4 v = *(const float4*)&Bm[(size_t)(k0 + k) * N + bn + n4 * 4];
            Bs[k][n4 * 4 + 0] = f2tf32(v.x);
            Bs[k][n4 * 4 + 1] = f2tf32(v.y);
            Bs[k][n4 * 4 + 2] = f2tf32(v.z);
            Bs[k][n4 * 4 + 3] = f2tf32(v.w);
        }
        __syncthreads();

        #pragma unroll
        for (int kk = 0; kk < 32; kk += 8) {
            uint32_t a[4][4], b[4][2];
            #pragma unroll
            for (int mt = 0; mt < 4; mt++) {
                int m = warpM + mt * 16;
                a[mt][0] = As[m + r0][kk + c0];
                a[mt][1] = As[m + r0 + 8][kk + c0];
                a[mt][2] = As[m + r0][kk + c0 + 4];
                a[mt][3] = As[m + r0 + 8][kk + c0 + 4];
            }
            #pragma unroll
            for (int nt = 0; nt < 4; nt++) {
                int n = warpN + nt * 8 + r0;
                b[nt][0] = Bs[kk + c0][n];
                b[nt][1] = Bs[kk + c0 + 4][n];
            }
            #pragma unroll
            for (int mt = 0; mt < 4; mt++)
                #pragma unroll
                for (int nt = 0; nt < 4; nt++)
                    mma_tf32(c[mt][nt], a[mt][0], a[mt][1], a[mt][2], a[mt][3],
                             b[nt][0], b[nt][1]);
        }
    }

    // Epilogue
    #pragma unroll
    for (int mt = 0; mt < 4; mt++) {
        #pragma unroll
        for (int nt = 0; nt < 4; nt++) {
            #pragma unroll
            for (int ci = 0; ci < 4; ci++) {
                int row = bm + warpM + mt * 16 + r0 + ((ci >= 2) ? 8 : 0);
                int col = bn + warpN + nt * 8 + c0 * 2 + (ci & 1);
                float v = c[mt][nt][ci] + bias[col];
                if (EPI == 1) v += resid[(size_t)row * N + col];
                if (EPI == 2) v = 0.5f * v * (1.0f + erff(v * 0.70710678118654752f));
                C[(size_t)row * N + col] = v;
            }
        }
    }
}

// ---------------- QK^T / 8 + ALiBi (TF32 mma) --------------------------------
// Block: 128 s x 128 t, K = 64 in two 32-chunks.
__global__ __launch_bounds__(256, 2)
void qk_tc(const float* __restrict__ qkv, float* __restrict__ scores)
{
    const int bh = blockIdx.z, b = bh >> 4, h = bh & 15;
    const int s0 = blockIdx.y * 128, t0 = blockIdx.x * 128;
    __shared__ uint32_t Qs[128][36];   // [s][d]
    __shared__ uint32_t Ks[128][36];   // [t][d]
    const int tid = threadIdx.x, warp = tid >> 5, lane = tid & 31;
    const int warpM = (warp & 1) * 64, warpN = (warp >> 1) * 32;
    const int r0 = lane >> 2, c0 = lane & 3;
    const size_t qbase = (size_t)b * Sq * (3 * Dm) + (size_t)h * DH;
    float c[4][4][4] = {};

    for (int d0 = 0; d0 < DH; d0 += 32) {
        __syncthreads();
        // Q and K chunks: 128 rows x 32 d each = 1024 float4 each -> 4 per thread each
        #pragma unroll
        for (int p = 0; p < 4; p++) {
            int idx = tid + p * 256;
            int r = idx >> 3, d4 = idx & 7;
            float4 vq = *(const float4*)&qkv[qbase + (size_t)(s0 + r) * (3 * Dm) + d0 + d4 * 4];
            float4 vk = *(const float4*)&qkv[qbase + (size_t)(t0 + r) * (3 * Dm) + Dm + d0 + d4 * 4];
            Qs[r][d4 * 4 + 0] = f2tf32(vq.x); Qs[r][d4 * 4 + 1] = f2tf32(vq.y);
            Qs[r][d4 * 4 + 2] = f2tf32(vq.z); Qs[r][d4 * 4 + 3] = f2tf32(vq.w);
            Ks[r][d4 * 4 + 0] = f2tf32(vk.x); Ks[r][d4 * 4 + 1] = f2tf32(vk.y);
            Ks[r][d4 * 4 + 2] = f2tf32(vk.z); Ks[r][d4 * 4 + 3] = f2tf32(vk.w);
        }
        __syncthreads();

        #pragma unroll
        for (int kk = 0; kk < 32; kk += 8) {
            uint32_t a[4][4], bfr[4][2];
            #pragma unroll
            for (int mt = 0; mt < 4; mt++) {
                int m = warpM + mt * 16;
                a[mt][0] = Qs[m + r0][kk + c0];
                a[mt][1] = Qs[m + r0 + 8][kk + c0];
                a[mt][2] = Qs[m + r0][kk + c0 + 4];
                a[mt][3] = Qs[m + r0 + 8][kk + c0 + 4];
            }
            #pragma unroll
            for (int nt = 0; nt < 4; nt++) {
                int n = warpN + nt * 8 + r0;
                bfr[nt][0] = Ks[n][kk + c0];
                bfr[nt][1] = Ks[n][kk + c0 + 4];
            }
            #pragma unroll
            for (int mt = 0; mt < 4; mt++)
                #pragma unroll
                for (int nt = 0; nt < 4; nt++)
                    mma_tf32(c[mt][nt], a[mt][0], a[mt][1], a[mt][2], a[mt][3],
                             bfr[nt][0], bfr[nt][1]);
        }
    }

    const float slope = exp2f(-0.5f * (float)(h + 1));
    const size_t obase = ((size_t)bh * Sq + s0) * Sq + t0;
    #pragma unroll
    for (int mt = 0; mt < 4; mt++) {
        #pragma unroll
        for (int nt = 0; nt < 4; nt++) {
            #pragma unroll
            for (int ci = 0; ci < 4; ci++) {
                int rr = warpM + mt * 16 + r0 + ((ci >= 2) ? 8 : 0);
                int cc = warpN + nt * 8 + c0 * 2 + (ci & 1);
                int si = s0 + rr, tj = t0 + cc;
                scores[obase + (size_t)rr * Sq + cc] =
                    c[mt][nt][ci] * 0.125f - slope * fabsf((float)(si - tj));
            }
        }
    }
}

// ---------------- softmax over last dim (row length 2048) --------------------
__global__ __launch_bounds__(256)
void softmax_kernel(float* __restrict__ scores)
{
    float* p = scores + (size_t)blockIdx.x * Sq;
    float v[8];
    float mx = -1e30f;
    #pragma unroll
    for (int i = 0; i < 8; i++) { v[i] = p[threadIdx.x + i * 256]; mx = fmaxf(mx, v[i]); }
    __shared__ float red[256];
    red[threadIdx.x] = mx; __syncthreads();
    #pragma unroll
    for (int s = 128; s > 0; s >>= 1) {
        if (threadIdx.x < s) red[threadIdx.x] = fmaxf(red[threadIdx.x], red[threadIdx.x + s]);
        __syncthreads();
    }
    mx = red[0]; __syncthreads();
    float sum = 0.f;
    #pragma unroll
    for (int i = 0; i < 8; i++) { v[i] = __expf(v[i] - mx); sum += v[i]; }
    red[threadIdx.x] = sum; __syncthreads();
    #pragma unroll
    for (int s = 128; s > 0; s >>= 1) {
        if (threadIdx.x < s) red[threadIdx.x] += red[threadIdx.x + s];
        __syncthreads();
    }
    float inv = 1.0f / red[0];
    #pragma unroll
    for (int i = 0; i < 8; i++) p[threadIdx.x + i * 256] = v[i] * inv;
}

// ---------------- attn @ V (TF32 mma) ----------------------------------------
// Block: 128 s x 64 d, K = 2048 in 32-chunks. Warps 4m x 2n, warp tile 32x32.
__global__ __launch_bounds__(256, 2)
void av_tc(const float* __restrict__ scores, const float* __restrict__ qkv,
           float* __restrict__ attnout)
{
    const int bh = blockIdx.y, b = bh >> 4, h = bh & 15;
    const int s0 = blockIdx.x * 128;
    __shared__ uint32_t Ps[128][36];   // [s][t]
    __shared__ uint32_t Vs[32][72];    // [t][d]
    const int tid = threadIdx.x, warp = tid >> 5, lane = tid & 31;
    const int warpM = (warp & 3) * 32, warpN = (warp >> 2) * 32;
    const int r0 = lane >> 2, c0 = lane & 3;
    const size_t srow = ((size_t)bh * Sq + s0) * Sq;
    const size_t vbase = (size_t)b * Sq * (3 * Dm) + 2 * Dm + (size_t)h * DH;
    float c[2][4][4] = {};

    for (int t0c = 0; t0c < Sq; t0c += 32) {
        __syncthreads();
        // P chunk: 128 s x 32 t = 1024 float4 -> 4 per thread
        #pragma unroll
        for (int p = 0; p < 4; p++) {
            int idx = tid + p * 256;
            int s = idx >> 3, t4 = idx & 7;
            float4 v = *(const float4*)&scores[srow + (size_t)s * Sq + t0c + t4 * 4];
            Ps[s][t4 * 4 + 0] = f2tf32(v.x); Ps[s][t4 * 4 + 1] = f2tf32(v.y);
            Ps[s][t4 * 4 + 2] = f2tf32(v.z); Ps[s][t4 * 4 + 3] = f2tf32(v.w);
        }
        // V chunk: 32 t x 64 d = 512 float4 -> 2 per thread
        #pragma unroll
        for (int p = 0; p < 2; p++) {
            int idx = tid + p * 256;
            int t = idx >> 4, d4 = idx & 15;
            float4 v = *(const float4*)&qkv[vbase + (size_t)(t0c + t) * (3 * Dm) + d4 * 4];
            Vs[t][d4 * 4 + 0] = f2tf32(v.x); Vs[t][d4 * 4 + 1] = f2tf32(v.y);
            Vs[t][d4 * 4 + 2] = f2tf32(v.z); Vs[t][d4 * 4 + 3] = f2tf32(v.w);
        }
        __syncthreads();

        #pragma unroll
        for (int kk = 0; kk < 32; kk += 8) {
            uint32_t a[2][4], bfr[4][2];
            #pragma unroll
            for (int mt = 0; mt < 2; mt++) {
                int m = warpM + mt * 16;
                a[mt][0] = Ps[m + r0][kk + c0];
                a[mt][1] = Ps[m + r0 + 8][kk + c0];
                a[mt][2] = Ps[m + r0][kk + c0 + 4];
                a[mt][3] = Ps[m + r0 + 8][kk + c0 + 4];
            }
            #pragma unroll
            for (int nt = 0; nt < 4; nt++) {
                int n = warpN + nt * 8 + r0;
                bfr[nt][0] = Vs[kk + c0][n];
                bfr[nt][1] = Vs[kk + c0 + 4][n];
            }
            #pragma unroll
            for (int mt = 0; mt < 2; mt++)
                #pragma unroll
                for (int nt = 0; nt < 4; nt++)
                    mma_tf32(c[mt][nt], a[mt][0], a[mt][1], a[mt][2], a[mt][3],
                             bfr[nt][0], bfr[nt][1]);
        }
    }

    const size_t obase = ((size_t)b * Sq + s0) * Dm + (size_t)h * DH;
    #pragma unroll
    for (int mt = 0; mt < 2; mt++) {
        #pragma unroll
        for (int nt = 0; nt < 4; nt++) {
            #pragma unroll
            for (int ci = 0; ci < 4; ci++) {
                int rr = warpM + mt * 16 + r0 + ((ci >= 2) ? 8 : 0);
                int cc = warpN + nt * 8 + c0 * 2 + (ci & 1);
                attnout[obase + (size_t)rr * Dm + cc] = c[mt][nt][ci];
            }
        }
    }
}

// ---------------- host driver ------------------------------------------------
extern "C" void kernel_launch(void* const* d_in, const int* in_sizes, int n_in,
                              void* d_out, int out_size)
{
    const float* x      = (const float*)d_in[0];
    const float* scale1 = (const float*)d_in[1];
    const float* scale2 = (const float*)d_in[2];
    const float* w_qkv  = (const float*)d_in[3];
    const float* b_qkv  = (const float*)d_in[4];
    const float* w_out  = (const float*)d_in[5];
    const float* b_out  = (const float*)d_in[6];
    const float* w1     = (const float*)d_in[7];
    const float* b1     = (const float*)d_in[8];
    const float* w2     = (const float*)d_in[9];
    const float* b2     = (const float*)d_in[10];
    float* out = (float*)d_out;

    void *p_xn, *p_qkv, *p_scores, *p_attnout, *p_x2, *p_h;
    cudaGetSymbolAddress(&p_xn, g_xn);
    cudaGetSymbolAddress(&p_qkv, g_qkv);
    cudaGetSymbolAddress(&p_scores, g_scores);
    cudaGetSymbolAddress(&p_attnout, g_attnout);
    cudaGetSymbolAddress(&p_x2, g_x2);
    cudaGetSymbolAddress(&p_h, g_h);
    float* xn      = (float*)p_xn;
    float* qkv     = (float*)p_qkv;
    float* scores  = (float*)p_scores;
    float* attnout = (float*)p_attnout;
    float* x2      = (float*)p_x2;
    float* hbuf    = (float*)p_h;

    // 1) RMSNorm 1
    rmsnorm_kernel<<<Mrows, 256>>>(x, scale1, xn);

    // 2) QKV projection
    gemm_tc<0><<<dim3(3 * Dm / 128, Mrows / 128), 256>>>(
        xn, w_qkv, b_qkv, nullptr, qkv, Mrows, 3 * Dm, Dm);

    // 3) scores = QK^T/8 + alibi
    qk_tc<<<dim3(Sq / 128, Sq / 128, BH), 256>>>(qkv, scores);

    // 4) softmax
    softmax_kernel<<<BH * Sq, 256>>>(scores);

    // 5) attn @ V
    av_tc<<<dim3(Sq / 128, BH), 256>>>(scores, qkv, attnout);

    // 6) out projection + residual
    gemm_tc<1><<<dim3(Dm / 128, Mrows / 128), 256>>>(
        attnout, w_out, b_out, x, x2, Mrows, Dm, Dm);

    // 7) RMSNorm 2
    rmsnorm_kernel<<<Mrows, 256>>>(x2, scale2, xn);

    // 8) FFN up + GELU
    gemm_tc<2><<<dim3(DFF / 128, Mrows / 128), 256>>>(
        xn, w1, b1, nullptr, hbuf, Mrows, DFF, Dm);

    // 9) FFN down + residual
    gemm_tc<1><<<dim3(Dm / 128, Mrows / 128), 256>>>(
        hbuf, w2, b2, x2, out, Mrows, Dm, DFF);
}

// round 3
// speedup vs baseline: 4.0063x; 1.2396x over previous
#include <cuda_runtime.h>
#include <cuda_bf16.h>
#include <math.h>
#include <stdint.h>

// Problem dims
#define Bz   2
#define Sq   2048
#define Dm   1024
#define Hn   16
#define DH   64
#define DFF  4096
#define Mrows (Bz * Sq)      // 4096
#define BH   (Bz * Hn)       // 32

// ---------------- scratch ----------------------------------------------------
__device__ float g_xn[(size_t)Mrows * Dm];
__device__ float g_qkv[(size_t)Mrows * 3 * Dm];
__device__ float g_attnout[(size_t)Mrows * Dm];
__device__ float g_x2[(size_t)Mrows * Dm];
__device__ float g_h[(size_t)Mrows * DFF];

// ---------------- helpers ----------------------------------------------------
__device__ __forceinline__ uint32_t f2tf32(float f) {
    uint32_t u;
    asm("cvt.rna.tf32.f32 %0, %1;" : "=r"(u) : "f"(f));
    return u;
}

__device__ __forceinline__ void mma_tf32(float c[4],
    uint32_t a0, uint32_t a1, uint32_t a2, uint32_t a3,
    uint32_t b0, uint32_t b1)
{
    asm volatile(
        "mma.sync.aligned.m16n8k8.row.col.f32.tf32.tf32.f32 "
        "{%0,%1,%2,%3}, {%4,%5,%6,%7}, {%8,%9}, {%0,%1,%2,%3};\n"
        : "+f"(c[0]), "+f"(c[1]), "+f"(c[2]), "+f"(c[3])
        : "r"(a0), "r"(a1), "r"(a2), "r"(a3), "r"(b0), "r"(b1));
}

// ---------------- RMSNorm ----------------------------------------------------
__global__ __launch_bounds__(256)
void rmsnorm_kernel(const float* __restrict__ x, const float* __restrict__ scale,
                    float* __restrict__ out)
{
    int row = blockIdx.x;
    const float* xr = x + (size_t)row * Dm;
    float ss = 0.f;
    #pragma unroll
    for (int i = threadIdx.x; i < Dm; i += 256) { float v = xr[i]; ss += v * v; }
    __shared__ float red[256];
    red[threadIdx.x] = ss; __syncthreads();
    #pragma unroll
    for (int s = 128; s > 0; s >>= 1) {
        if (threadIdx.x < s) red[threadIdx.x] += red[threadIdx.x + s];
        __syncthreads();
    }
    float rms = rsqrtf(red[0] * (1.0f / Dm) + 1e-8f);
    float* orow = out + (size_t)row * Dm;
    #pragma unroll
    for (int i = threadIdx.x; i < Dm; i += 256)
        orow[i] = scale[i] * xr[i] * rms;
}

// ---------------- TF32 tensor-core GEMM: C = A[M,K] @ B[K,N] -----------------
// EPI: 0 = +bias, 1 = +bias+residual, 2 = +bias then exact gelu
template<int EPI>
__global__ __launch_bounds__(256, 2)
void gemm_tc(const float* __restrict__ A, const float* __restrict__ Bm,
             const float* __restrict__ bias, const float* __restrict__ resid,
             float* __restrict__ C, int M, int N, int K)
{
    __shared__ uint32_t As[128][36];
    __shared__ uint32_t Bs[32][136];
    const int tid = threadIdx.x, warp = tid >> 5, lane = tid & 31;
    const int bm = blockIdx.y * 128, bn = blockIdx.x * 128;
    const int warpM = (warp & 1) * 64, warpN = (warp >> 1) * 32;
    const int r0 = lane >> 2, c0 = lane & 3;
    float c[4][4][4] = {};

    for (int k0 = 0; k0 < K; k0 += 32) {
        __syncthreads();
        #pragma unroll
        for (int p = 0; p < 4; p++) {
            int idx = tid + p * 256;
            int m = idx >> 3, k4 = idx & 7;
            float4 v = *(const float4*)&A[(size_t)(bm + m) * K + k0 + k4 * 4];
            As[m][k4 * 4 + 0] = f2tf32(v.x);
            As[m][k4 * 4 + 1] = f2tf32(v.y);
            As[m][k4 * 4 + 2] = f2tf32(v.z);
            As[m][k4 * 4 + 3] = f2tf32(v.w);
        }
        #pragma unroll
        for (int p = 0; p < 4; p++) {
            int idx = tid + p * 256;
            int k = idx >> 5, n4 = idx & 31;
            float4 v = *(const float4*)&Bm[(size_t)(k0 + k) * N + bn + n4 * 4];
            Bs[k][n4 * 4 + 0] = f2tf32(v.x);
            Bs[k][n4 * 4 + 1] = f2tf32(v.y);
            Bs[k][n4 * 4 + 2] = f2tf32(v.z);
            Bs[k][n4 * 4 + 3] = f2tf32(v.w);
        }
        __syncthreads();

        #pragma unroll
        for (int kk = 0; kk < 32; kk += 8) {
            uint32_t a[4][4], b[4][2];
            #pragma unroll
            for (int mt = 0; mt < 4; mt++) {
                int m = warpM + mt * 16;
                a[mt][0] = As[m + r0][kk + c0];
                a[mt][1] = As[m + r0 + 8][kk + c0];
                a[mt][2] = As[m + r0][kk + c0 + 4];
                a[mt][3] = As[m + r0 + 8][kk + c0 + 4];
            }
            #pragma unroll
            for (int nt = 0; nt < 4; nt++) {
                int n = warpN + nt * 8 + r0;
                b[nt][0] = Bs[kk + c0][n];
                b[nt][1] = Bs[kk + c0 + 4][n];
            }
            #pragma unroll
            for (int mt = 0; mt < 4; mt++)
                #pragma unroll
                for (int nt = 0; nt < 4; nt++)
                    mma_tf32(c[mt][nt], a[mt][0], a[mt][1], a[mt][2], a[mt][3],
                             b[nt][0], b[nt][1]);
        }
    }

    #pragma unroll
    for (int mt = 0; mt < 4; mt++) {
        #pragma unroll
        for (int nt = 0; nt < 4; nt++) {
            #pragma unroll
            for (int ci = 0; ci < 4; ci++) {
                int row = bm + warpM + mt * 16 + r0 + ((ci >= 2) ? 8 : 0);
                int col = bn + warpN + nt * 8 + c0 * 2 + (ci & 1);
                float v = c[mt][nt][ci] + bias[col];
                if (EPI == 1) v += resid[(size_t)row * N + col];
                if (EPI == 2) v = 0.5f * v * (1.0f + erff(v * 0.70710678118654752f));
                C[(size_t)row * N + col] = v;
            }
        }
    }
}

// ---------------- fused flash attention --------------------------------------
// Per CTA: 128 query rows (8 warps x 16), loop KV in 64-row tiles.
// scores = QK^T/8 - slope|s-t|, online softmax, O = P@V, all in one pass.
#define QS_STRIDE 68
#define KS_STRIDE 68
#define VS_STRIDE 72
#define PS_STRIDE 68
#define FLASH_SMEM ((128 * QS_STRIDE + 64 * KS_STRIDE + 64 * VS_STRIDE + 128 * PS_STRIDE) * 4)

__global__ __launch_bounds__(256, 2)
void flash_attn(const float* __restrict__ qkv, float* __restrict__ attnout)
{
    extern __shared__ uint32_t sm[];
    uint32_t* Qs = sm;                        // [128][68]  tf32
    uint32_t* Ks = Qs + 128 * QS_STRIDE;      // [64][68]
    uint32_t* Vs = Ks + 64 * KS_STRIDE;       // [64][72]
    uint32_t* Ps = Vs + 64 * VS_STRIDE;       // [128][68]

    const int bh = blockIdx.y, b = bh >> 4, h = bh & 15;
    const int q0 = blockIdx.x * 128;
    const int tid = threadIdx.x, warp = tid >> 5, lane = tid & 31;
    const int r0 = lane >> 2, c0 = lane & 3;
    const int qrow = warp * 16;
    const float slope = exp2f(-0.5f * (float)(h + 1));
    const size_t base = (size_t)b * Sq * (3 * Dm) + (size_t)h * DH;

    // Load Q tile (persistent): 128 rows x 64 d
    #pragma unroll
    for (int p = 0; p < 8; p++) {
        int idx = tid + p * 256;
        int r = idx >> 4, d4 = idx & 15;
        float4 v = *(const float4*)&qkv[base + (size_t)(q0 + r) * (3 * Dm) + d4 * 4];
        uint32_t* dst = &Qs[r * QS_STRIDE + d4 * 4];
        dst[0] = f2tf32(v.x); dst[1] = f2tf32(v.y);
        dst[2] = f2tf32(v.z); dst[3] = f2tf32(v.w);
    }

    float m_i[2] = {-1e30f, -1e30f};
    float l_i[2] = {0.f, 0.f};
    float o[8][4] = {};

    for (int t0 = 0; t0 < Sq; t0 += 64) {
        __syncthreads();
        // Load K,V tiles: 64 rows x 64 d each
        #pragma unroll
        for (int p = 0; p < 4; p++) {
            int idx = tid + p * 256;
            int r = idx >> 4, d4 = idx & 15;
            const float* src = &qkv[base + (size_t)(t0 + r) * (3 * Dm) + d4 * 4];
            float4 vk = *(const float4*)(src + Dm);
            float4 vv = *(const float4*)(src + 2 * Dm);
            uint32_t* dk = &Ks[r * KS_STRIDE + d4 * 4];
            dk[0] = f2tf32(vk.x); dk[1] = f2tf32(vk.y);
            dk[2] = f2tf32(vk.z); dk[3] = f2tf32(vk.w);
            uint32_t* dv = &Vs[r * VS_STRIDE + d4 * 4];
            dv[0] = f2tf32(vv.x); dv[1] = f2tf32(vv.y);
            dv[2] = f2tf32(vv.z); dv[3] = f2tf32(vv.w);
        }
        __syncthreads();

        // S = Q @ K^T  (warp: 16 rows x 64 t)
        float s[8][4] = {};
        #pragma unroll
        for (int kk = 0; kk < 64; kk += 8) {
            uint32_t a0 = Qs[(qrow + r0) * QS_STRIDE + kk + c0];
            uint32_t a1 = Qs[(qrow + r0 + 8) * QS_STRIDE + kk + c0];
            uint32_t a2 = Qs[(qrow + r0) * QS_STRIDE + kk + c0 + 4];
            uint32_t a3 = Qs[(qrow + r0 + 8) * QS_STRIDE + kk + c0 + 4];
            #pragma unroll
            for (int nt = 0; nt < 8; nt++) {
                uint32_t b0 = Ks[(nt * 8 + r0) * KS_STRIDE + kk + c0];
                uint32_t b1 = Ks[(nt * 8 + r0) * KS_STRIDE + kk + c0 + 4];
                mma_tf32(s[nt], a0, a1, a2, a3, b0, b1);
            }
        }

        // scale + alibi + row max (rows r0 and r0+8 of this warp's 16)
        const int si0 = q0 + qrow + r0, si1 = si0 + 8;
        float mx0 = -1e30f, mx1 = -1e30f;
        #pragma unroll
        for (int nt = 0; nt < 8; nt++) {
            int tj = t0 + nt * 8 + c0 * 2;
            s[nt][0] = s[nt][0] * 0.125f - slope * fabsf((float)(si0 - tj));
            s[nt][1] = s[nt][1] * 0.125f - slope * fabsf((float)(si0 - tj - 1));
            s[nt][2] = s[nt][2] * 0.125f - slope * fabsf((float)(si1 - tj));
            s[nt][3] = s[nt][3] * 0.125f - slope * fabsf((float)(si1 - tj - 1));
            mx0 = fmaxf(mx0, fmaxf(s[nt][0], s[nt][1]));
            mx1 = fmaxf(mx1, fmaxf(s[nt][2], s[nt][3]));
        }
        mx0 = fmaxf(mx0, __shfl_xor_sync(0xffffffffu, mx0, 1));
        mx0 = fmaxf(mx0, __shfl_xor_sync(0xffffffffu, mx0, 2));
        mx1 = fmaxf(mx1, __shfl_xor_sync(0xffffffffu, mx1, 1));
        mx1 = fmaxf(mx1, __shfl_xor_sync(0xffffffffu, mx1, 2));

        float mn0 = fmaxf(m_i[0], mx0), mn1 = fmaxf(m_i[1], mx1);
        float corr0 = __expf(m_i[0] - mn0), corr1 = __expf(m_i[1] - mn1);
        m_i[0] = mn0; m_i[1] = mn1;

        float sum0 = 0.f, sum1 = 0.f;
        #pragma unroll
        for (int nt = 0; nt < 8; nt++) {
            s[nt][0] = __expf(s[nt][0] - mn0);
            s[nt][1] = __expf(s[nt][1] - mn0);
            s[nt][2] = __expf(s[nt][2] - mn1);
            s[nt][3] = __expf(s[nt][3] - mn1);
            sum0 += s[nt][0] + s[nt][1];
            sum1 += s[nt][2] + s[nt][3];
            uint32_t* d0 = &Ps[(qrow + r0) * PS_STRIDE + nt * 8 + c0 * 2];
            d0[0] = f2tf32(s[nt][0]); d0[1] = f2tf32(s[nt][1]);
            uint32_t* d1 = &Ps[(qrow + r0 + 8) * PS_STRIDE + nt * 8 + c0 * 2];
            d1[0] = f2tf32(s[nt][2]); d1[1] = f2tf32(s[nt][3]);
        }
        sum0 += __shfl_xor_sync(0xffffffffu, sum0, 1);
        sum0 += __shfl_xor_sync(0xffffffffu, sum0, 2);
        sum1 += __shfl_xor_sync(0xffffffffu, sum1, 1);
        sum1 += __shfl_xor_sync(0xffffffffu, sum1, 2);
        l_i[0] = l_i[0] * corr0 + sum0;
        l_i[1] = l_i[1] * corr1 + sum1;
        #pragma unroll
        for (int nt = 0; nt < 8; nt++) {
            o[nt][0] *= corr0; o[nt][1] *= corr0;
            o[nt][2] *= corr1; o[nt][3] *= corr1;
        }
        __syncwarp();  // Ps visible to whole warp

        // O += P @ V  (k over 64 kv rows, n over 64 d)
        #pragma unroll
        for (int kk = 0; kk < 64; kk += 8) {
            uint32_t a0 = Ps[(qrow + r0) * PS_STRIDE + kk + c0];
            uint32_t a1 = Ps[(qrow + r0 + 8) * PS_STRIDE + kk + c0];
            uint32_t a2 = Ps[(qrow + r0) * PS_STRIDE + kk + c0 + 4];
            uint32_t a3 = Ps[(qrow + r0 + 8) * PS_STRIDE + kk + c0 + 4];
            #pragma unroll
            for (int nt = 0; nt < 8; nt++) {
                uint32_t b0 = Vs[(kk + c0) * VS_STRIDE + nt * 8 + r0];
                uint32_t b1 = Vs[(kk + c0 + 4) * VS_STRIDE + nt * 8 + r0];
                mma_tf32(o[nt], a0, a1, a2, a3, b0, b1);
            }
        }
    }

    // Normalize and write out: attnout[(b*S + s)*D + h*64 + d]
    float inv0 = 1.f / l_i[0], inv1 = 1.f / l_i[1];
    size_t obase = ((size_t)b * Sq + q0 + qrow) * Dm + (size_t)h * DH;
    #pragma unroll
    for (int nt = 0; nt < 8; nt++) {
        int d = nt * 8 + c0 * 2;
        attnout[obase + (size_t)r0 * Dm + d]           = o[nt][0] * inv0;
        attnout[obase + (size_t)r0 * Dm + d + 1]       = o[nt][1] * inv0;
        attnout[obase + (size_t)(r0 + 8) * Dm + d]     = o[nt][2] * inv1;
        attnout[obase + (size_t)(r0 + 8) * Dm + d + 1] = o[nt][3] * inv1;
    }
}

// ---------------- host driver ------------------------------------------------
extern "C" void kernel_launch(void* const* d_in, const int* in_sizes, int n_in,
                              void* d_out, int out_size)
{
    const float* x      = (const float*)d_in[0];
    const float* scale1 = (const float*)d_in[1];
    const float* scale2 = (const float*)d_in[2];
    const float* w_qkv  = (const float*)d_in[3];
    const float* b_qkv  = (const float*)d_in[4];
    const float* w_out  = (const float*)d_in[5];
    const float* b_out  = (const float*)d_in[6];
    const float* w1     = (const float*)d_in[7];
    const float* b1     = (const float*)d_in[8];
    const float* w2     = (const float*)d_in[9];
    const float* b2     = (const float*)d_in[10];
    float* out = (float*)d_out;

    void *p_xn, *p_qkv, *p_attnout, *p_x2, *p_h;
    cudaGetSymbolAddress(&p_xn, g_xn);
    cudaGetSymbolAddress(&p_qkv, g_qkv);
    cudaGetSymbolAddress(&p_attnout, g_attnout);
    cudaGetSymbolAddress(&p_x2, g_x2);
    cudaGetSymbolAddress(&p_h, g_h);
    float* xn      = (float*)p_xn;
    float* qkv     = (float*)p_qkv;
    float* attnout = (float*)p_attnout;
    float* x2      = (float*)p_x2;
    float* hbuf    = (float*)p_h;

    cudaFuncSetAttribute(flash_attn, cudaFuncAttributeMaxDynamicSharedMemorySize,
                         FLASH_SMEM);

    // 1) RMSNorm 1
    rmsnorm_kernel<<<Mrows, 256>>>(x, scale1, xn);

    // 2) QKV projection
    gemm_tc<0><<<dim3(3 * Dm / 128, Mrows / 128), 256>>>(
        xn, w_qkv, b_qkv, nullptr, qkv, Mrows, 3 * Dm, Dm);

    // 3-5) fused attention
    flash_attn<<<dim3(Sq / 128, BH), 256, FLASH_SMEM>>>(qkv, attnout);

    // 6) out projection + residual
    gemm_tc<1><<<dim3(Dm / 128, Mrows / 128), 256>>>(
        attnout, w_out, b_out, x, x2, Mrows, Dm, Dm);

    // 7) RMSNorm 2
    rmsnorm_kernel<<<Mrows, 256>>>(x2, scale2, xn);

    // 8) FFN up + GELU
    gemm_tc<2><<<dim3(DFF / 128, Mrows / 128), 256>>>(
        xn, w1, b1, nullptr, hbuf, Mrows, DFF, Dm);

    // 9) FFN down + residual
    gemm_tc<1><<<dim3(Dm / 128, Mrows / 128), 256>>>(
        hbuf, w2, b2, x2, out, Mrows, Dm, DFF);
}